// round 10
// baseline (speedup 1.0000x reference)
#include <cuda_runtime.h>
#include <cuda_bf16.h>
#include <cstdint>

// Problem dims
#define B_ 16
#define L_ 512
#define H_ 8
#define E_ 64
#define BH_ (B_ * H_)          // 128

// ===================== helpers =====================
__device__ __forceinline__ uint32_t smem_u32(const void* p) {
    uint32_t a;
    asm("{ .reg .u64 t; cvta.to.shared.u64 t, %1; cvt.u32.u64 %0, t; }"
        : "=r"(a) : "l"(p));
    return a;
}
__device__ __forceinline__ uint32_t bf16x2_of(float v0, float v1) {
    uint32_t r;
    asm("cvt.rn.bf16x2.f32 %0, %1, %2;" : "=r"(r) : "f"(v1), "f"(v0));
    return r;
}
__device__ __forceinline__ uint32_t lds32(uint32_t addr) {
    uint32_t v;
    asm volatile("ld.shared.b32 %0, [%1];" : "=r"(v) : "r"(addr));
    return v;
}
__device__ __forceinline__ float4 lds128(uint32_t addr) {
    float4 v;
    asm volatile("ld.shared.v4.f32 {%0,%1,%2,%3}, [%4];"
                 : "=f"(v.x), "=f"(v.y), "=f"(v.z), "=f"(v.w) : "r"(addr));
    return v;
}
__device__ __forceinline__ void sts64f(uint32_t addr, float c0, float c1) {
    asm volatile("st.shared.v2.f32 [%0], {%1,%2};" :: "r"(addr), "f"(c0), "f"(c1) : "memory");
}
__device__ __forceinline__ void mma16816(float* c, const uint32_t* a, const uint32_t* b) {
    asm volatile(
        "mma.sync.aligned.m16n8k16.row.col.f32.bf16.bf16.f32 "
        "{%0,%1,%2,%3}, {%4,%5,%6,%7}, {%8,%9}, {%0,%1,%2,%3};"
        : "+f"(c[0]), "+f"(c[1]), "+f"(c[2]), "+f"(c[3])
        : "r"(a[0]), "r"(a[1]), "r"(a[2]), "r"(a[3]), "r"(b[0]), "r"(b[1]));
}
__device__ __forceinline__ float exp_acc(float x) {
    float m = __fmul_rn(x, 1.4426950408889634f);
    float t = __fmaf_rn(x, 1.925962991e-8f, m);
    float r;
    asm("ex2.approx.ftz.f32 %0, %1;" : "=f"(r) : "f"(t));
    return r;
}
__device__ __forceinline__ void split_store4(char* smem, uint32_t offHi, uint32_t offLo, float4 v) {
    uint32_t h01 = bf16x2_of(v.x, v.y);
    uint32_t h23 = bf16x2_of(v.z, v.w);
    float l0 = v.x - __uint_as_float(h01 << 16);
    float l1 = v.y - __uint_as_float(h01 & 0xFFFF0000u);
    float l2 = v.z - __uint_as_float(h23 << 16);
    float l3 = v.w - __uint_as_float(h23 & 0xFFFF0000u);
    *(uint2*)(smem + offHi) = make_uint2(h01, h23);
    *(uint2*)(smem + offLo) = make_uint2(bf16x2_of(l0, l1), bf16x2_of(l2, l3));
}
__device__ __forceinline__ void split2(float2 v, uint32_t& hi, uint32_t& lo) {
    hi = bf16x2_of(v.x, v.y);
    float l0 = v.x - __uint_as_float(hi << 16);
    float l1 = v.y - __uint_as_float(hi & 0xFFFF0000u);
    lo = bf16x2_of(l0, l1);
}

// ======================================================================
// Fused megakernel per (bh, lt):  sg(fp64) -> prior+sigf -> QK^T MMA ->
// softmax -> series -> P frags reused as A operand -> PV MMA -> V out.
// ======================================================================
#define F_ST   72
#define F_QHI  0
#define F_QLO  9216
#define F_KHI  18432
#define F_KLO  92160
#define F_SG   165888            // 64 * 4
#define F_RED0 166144
#define F_RED1 167168
// PV phase (reuses [0, 133120) after QK done):
#define PVT_ST 1040
#define PVT_HI 0
#define PVT_LO 66560
#define STG_OFF 133120           // 4 x 64 x 68 floats
#define STG_WN  17408            // 64*68*4
#define F_SMEM  202752           // STG_OFF + 4*STG_WN

__global__ void __launch_bounds__(512, 1)
anomaly_fused_kernel(const float* __restrict__ q, const float* __restrict__ k,
                     const float* __restrict__ v, const float* __restrict__ sigma,
                     float* __restrict__ vout, float* __restrict__ series,
                     float* __restrict__ prior, float* __restrict__ sigf)
{
    extern __shared__ char smem[];
    const uint32_t sb = smem_u32(smem);
    const int tid  = threadIdx.x;
    const int wid  = tid >> 5;
    const int lane = tid & 31;
    const int wm   = wid >> 2;
    const int wn   = wid & 3;
    const int r    = lane >> 2;
    const int qc   = lane & 3;

    const int bh = blockIdx.y;
    const int b  = bh >> 3;
    const int h  = bh & 7;
    const int lt = blockIdx.x;
    const int lbase = lt * 64;

    // ---- sigma -> bandwidth for this CTA's 64 rows (fp64, 64 threads) ----
    if (tid < 64) {
        int gl = lbase + tid;
        double xd = (double)sigma[((size_t)b * L_ + gl) * H_ + h];
        double sd = 1.0 / (1.0 + exp(-5.0 * xd));
        float sgm = (float)(sd + 1e-5);
        double P  = exp2((double)sgm * 1.5849625007211562);  // 3^sgm
        *(float*)(smem + F_SG + tid * 4) = (float)P - 1.0f;
    }

    const float* qbase = q + (size_t)(b * L_ + lbase) * (H_ * E_) + h * E_;
    const float* kbase = k + (size_t)(b * L_) * (H_ * E_) + h * E_;

#pragma unroll
    for (int i = tid; i < 1024; i += 512) {
        int row = i >> 4, e4 = i & 15;
        uint32_t off = (uint32_t)row * (F_ST * 2) + e4 * 8;
        float4 va = *(const float4*)(qbase + (size_t)row * (H_ * E_) + e4 * 4);
        va.x *= 0.125f; va.y *= 0.125f; va.z *= 0.125f; va.w *= 0.125f;
        split_store4(smem, F_QHI + off, F_QLO + off, va);
    }
#pragma unroll
    for (int i = tid; i < 8192; i += 512) {
        int row = i >> 4, e4 = i & 15;
        uint32_t off = (uint32_t)row * (F_ST * 2) + e4 * 8;
        float4 vb = *(const float4*)(kbase + (size_t)row * (H_ * E_) + e4 * 4);
        split_store4(smem, F_KHI + off, F_KLO + off, vb);
    }
    __syncthreads();

    // ---- prior + sigma_full (stores drain during MMA phase) ----
    {
#pragma unroll
        for (int i = tid; i < 8192; i += 512) {
            int row = i >> 7, c4 = (i & 127) * 4;
            const float sg = *(const float*)(smem + F_SG + row * 4);
            const float cv   = __fdiv_rn(0.3989422804014327f, sg);
            const float rinv = __fdiv_rn(1.0f, __fmul_rn(2.0f, __fmul_rn(sg, sg)));
            const int gl = lbase + row;
            float d0 = (float)(gl - c4);
            float d1 = (float)(gl - c4 - 1);
            float d2 = (float)(gl - c4 - 2);
            float d3 = (float)(gl - c4 - 3);
            float4 pv;
            pv.x = __fmul_rn(cv, exp_acc(-__fmul_rn(__fmul_rn(d0, d0), rinv)));
            pv.y = __fmul_rn(cv, exp_acc(-__fmul_rn(__fmul_rn(d1, d1), rinv)));
            pv.z = __fmul_rn(cv, exp_acc(-__fmul_rn(__fmul_rn(d2, d2), rinv)));
            pv.w = __fmul_rn(cv, exp_acc(-__fmul_rn(__fmul_rn(d3, d3), rinv)));
            size_t base = ((size_t)bh * L_ + gl) * L_ + c4;
            *(float4*)(prior + base) = pv;
            *(float4*)(sigf + base)  = make_float4(sg, sg, sg, sg);
        }
    }

    // ---- QK^T MMA (3-product bf16 split) ----
    float acc[16][4];
#pragma unroll
    for (int nb = 0; nb < 16; nb++)
#pragma unroll
        for (int x = 0; x < 4; x++) acc[nb][x] = 0.f;

    {
        const uint32_t abase[3] = {sb + F_QHI, sb + F_QHI, sb + F_QLO};
        const uint32_t bbase[3] = {sb + F_KHI, sb + F_KLO, sb + F_KHI};
#pragma unroll
        for (int pr = 0; pr < 3; pr++) {
            uint32_t Ab = abase[pr], Bb = bbase[pr];
#pragma unroll
            for (int ks = 0; ks < 4; ks++) {
                uint32_t kByte = ks * 32 + qc * 4;
                uint32_t a[4];
                uint32_t ad = Ab + (uint32_t)(wm * 16 + r) * (F_ST * 2) + kByte;
                a[0] = lds32(ad);
                a[1] = lds32(ad + 8 * F_ST * 2);
                a[2] = lds32(ad + 16);
                a[3] = lds32(ad + 8 * F_ST * 2 + 16);
#pragma unroll
                for (int nb = 0; nb < 16; nb++) {
                    uint32_t bd = Bb + (uint32_t)(wn * 128 + nb * 8 + r) * (F_ST * 2) + kByte;
                    uint32_t bf[2];
                    bf[0] = lds32(bd);
                    bf[1] = lds32(bd + 16);
                    mma16816(acc[nb], a, bf);
                }
            }
        }
    }

    // ---- softmax over 512 cols ----
    const int row0 = wm * 16 + r;
    const int row1 = row0 + 8;

    float mx0 = -1e30f, mx1 = -1e30f;
#pragma unroll
    for (int nb = 0; nb < 16; nb++) {
        mx0 = fmaxf(mx0, fmaxf(acc[nb][0], acc[nb][1]));
        mx1 = fmaxf(mx1, fmaxf(acc[nb][2], acc[nb][3]));
    }
#pragma unroll
    for (int o = 1; o <= 2; o <<= 1) {
        mx0 = fmaxf(mx0, __shfl_xor_sync(0xffffffffu, mx0, o));
        mx1 = fmaxf(mx1, __shfl_xor_sync(0xffffffffu, mx1, o));
    }
    if (qc == 0) {
        *(float*)(smem + F_RED0 + (row0 * 4 + wn) * 4) = mx0;
        *(float*)(smem + F_RED0 + (row1 * 4 + wn) * 4) = mx1;
    }
    __syncthreads();
    {
        const float* rd = (const float*)(smem + F_RED0);
        mx0 = fmaxf(fmaxf(rd[row0 * 4 + 0], rd[row0 * 4 + 1]),
                    fmaxf(rd[row0 * 4 + 2], rd[row0 * 4 + 3]));
        mx1 = fmaxf(fmaxf(rd[row1 * 4 + 0], rd[row1 * 4 + 1]),
                    fmaxf(rd[row1 * 4 + 2], rd[row1 * 4 + 3]));
    }

    float s0 = 0.f, s1 = 0.f;
#pragma unroll
    for (int nb = 0; nb < 16; nb++) {
        acc[nb][0] = exp_acc(acc[nb][0] - mx0); s0 += acc[nb][0];
        acc[nb][1] = exp_acc(acc[nb][1] - mx0); s0 += acc[nb][1];
        acc[nb][2] = exp_acc(acc[nb][2] - mx1); s1 += acc[nb][2];
        acc[nb][3] = exp_acc(acc[nb][3] - mx1); s1 += acc[nb][3];
    }
#pragma unroll
    for (int o = 1; o <= 2; o <<= 1) {
        s0 += __shfl_xor_sync(0xffffffffu, s0, o);
        s1 += __shfl_xor_sync(0xffffffffu, s1, o);
    }
    if (qc == 0) {
        *(float*)(smem + F_RED1 + (row0 * 4 + wn) * 4) = s0;
        *(float*)(smem + F_RED1 + (row1 * 4 + wn) * 4) = s1;
    }
    __syncthreads();
    {
        const float* rd = (const float*)(smem + F_RED1);
        s0 = (rd[row0 * 4 + 0] + rd[row0 * 4 + 1]) + (rd[row0 * 4 + 2] + rd[row0 * 4 + 3]);
        s1 = (rd[row1 * 4 + 0] + rd[row1 * 4 + 1]) + (rd[row1 * 4 + 2] + rd[row1 * 4 + 3]);
    }
    const float inv0 = __fdiv_rn(1.f, s0);
    const float inv1 = __fdiv_rn(1.f, s1);

    // ---- write series + split P to bf16 hi/lo fragments (in regs) ----
    uint32_t phi[16][2], plo[16][2];
    {
        float* o0 = series + ((size_t)bh * L_ + lbase + row0) * L_ + wn * 128 + qc * 2;
        float* o1 = series + ((size_t)bh * L_ + lbase + row1) * L_ + wn * 128 + qc * 2;
#pragma unroll
        for (int nb = 0; nb < 16; nb++) {
            float v0 = acc[nb][0] * inv0, v1 = acc[nb][1] * inv0;
            float v2 = acc[nb][2] * inv1, v3 = acc[nb][3] * inv1;
            *(float2*)(o0 + nb * 8) = make_float2(v0, v1);
            *(float2*)(o1 + nb * 8) = make_float2(v2, v3);
            split2(make_float2(v0, v1), phi[nb][0], plo[nb][0]);
            split2(make_float2(v2, v3), phi[nb][1], plo[nb][1]);
        }
    }
    __syncthreads();   // all warps done with Q/K smem + RED

    // ---- load V^T (d x s) hi/lo into smem [reuses Q/K region] ----
    {
        const float* vbase = v + (size_t)b * L_ * H_ * E_ + h * E_;
#pragma unroll
        for (int i = tid; i < 8192; i += 512) {
            int s = i >> 4, d4 = i & 15;
            float4 vv = *(const float4*)(vbase + (size_t)s * (H_ * E_) + d4 * 4);
            float xs[4] = {vv.x, vv.y, vv.z, vv.w};
#pragma unroll
            for (int j = 0; j < 4; j++) {
                __nv_bfloat16 hb = __float2bfloat16(xs[j]);
                float hf = __bfloat162float(hb);
                __nv_bfloat16 lb = __float2bfloat16(xs[j] - hf);
                uint32_t off = (uint32_t)(d4 * 4 + j) * PVT_ST + s * 2;
                *(__nv_bfloat16*)(smem + PVT_HI + off) = hb;
                *(__nv_bfloat16*)(smem + PVT_LO + off) = lb;
            }
        }
    }
    __syncthreads();

    // ---- PV MMA: P fragments (A) x V^T (B), k = s over this warp's 128 ----
    float acc2[8][4];
#pragma unroll
    for (int nb = 0; nb < 8; nb++)
#pragma unroll
        for (int x = 0; x < 4; x++) acc2[nb][x] = 0.f;

#pragma unroll
    for (int ksb = 0; ksb < 8; ksb++) {
        uint32_t ahi[4] = {phi[2 * ksb][0], phi[2 * ksb][1],
                           phi[2 * ksb + 1][0], phi[2 * ksb + 1][1]};
        uint32_t alo[4] = {plo[2 * ksb][0], plo[2 * ksb][1],
                           plo[2 * ksb + 1][0], plo[2 * ksb + 1][1]};
        const uint32_t kByte = (uint32_t)(wn * 128 + ksb * 16) * 2 + qc * 4;
#pragma unroll
        for (int nb = 0; nb < 8; nb++) {
            uint32_t bd = sb + (uint32_t)(nb * 8 + r) * PVT_ST + kByte;
            uint32_t bhi[2], blo[2];
            bhi[0] = lds32(bd + PVT_HI);
            bhi[1] = lds32(bd + PVT_HI + 16);
            blo[0] = lds32(bd + PVT_LO);
            blo[1] = lds32(bd + PVT_LO + 16);
            mma16816(acc2[nb], ahi, bhi);
            mma16816(acc2[nb], alo, bhi);
            mma16816(acc2[nb], ahi, blo);
        }
    }

    // ---- stage partials (per wn), reduce, write V ----
    {
        uint32_t st = sb + STG_OFF + (uint32_t)wn * STG_WN;
#pragma unroll
        for (int nb = 0; nb < 8; nb++) {
            uint32_t ad = st + (uint32_t)(wm * 16 + r) * 272 + (nb * 8 + qc * 2) * 4;
            sts64f(ad, acc2[nb][0], acc2[nb][1]);
            sts64f(ad + 8 * 272, acc2[nb][2], acc2[nb][3]);
        }
    }
    __syncthreads();
    {
#pragma unroll
        for (int i = tid; i < 1024; i += 512) {
            int row = i >> 4, d4 = i & 15;
            uint32_t a0 = sb + STG_OFF + (uint32_t)row * 272 + d4 * 16;
            float4 p0 = lds128(a0);
            float4 p1 = lds128(a0 + STG_WN);
            float4 p2 = lds128(a0 + 2 * STG_WN);
            float4 p3 = lds128(a0 + 3 * STG_WN);
            float4 sum;
            sum.x = (p0.x + p1.x) + (p2.x + p3.x);
            sum.y = (p0.y + p1.y) + (p2.y + p3.y);
            sum.z = (p0.z + p1.z) + (p2.z + p3.z);
            sum.w = (p0.w + p1.w) + (p2.w + p3.w);
            *(float4*)(vout + (((size_t)b * L_ + lbase + row) * H_ + h) * E_ + d4 * 4) = sum;
        }
    }
}

// ======================================================================
extern "C" void kernel_launch(void* const* d_in, const int* in_sizes, int n_in,
                              void* d_out, int out_size)
{
    const float* q     = (const float*)d_in[0];
    const float* k     = (const float*)d_in[1];
    const float* v     = (const float*)d_in[2];
    const float* sigma = (const float*)d_in[3];

    float* out    = (float*)d_out;
    float* Vout   = out;                                        // [B,L,H,E]
    float* series = Vout + (size_t)B_ * L_ * H_ * E_;           // [B,H,L,L]
    float* prior  = series + (size_t)BH_ * L_ * L_;             // [B,H,L,L]
    float* sigf   = prior + (size_t)BH_ * L_ * L_;              // [B,H,L,L]

    cudaFuncSetAttribute(anomaly_fused_kernel,
                         cudaFuncAttributeMaxDynamicSharedMemorySize, F_SMEM);

    dim3 g1(8, BH_);
    anomaly_fused_kernel<<<g1, 512, F_SMEM>>>(q, k, v, sigma, Vout, series, prior, sigf);
}

// round 11
// speedup vs baseline: 1.1576x; 1.1576x over previous
#include <cuda_runtime.h>
#include <cuda_bf16.h>
#include <cstdint>

// Problem dims
#define B_ 16
#define L_ 512
#define H_ 8
#define E_ 64
#define BH_ (B_ * H_)          // 128

// ===================== helpers =====================
__device__ __forceinline__ uint32_t smem_u32(const void* p) {
    uint32_t a;
    asm("{ .reg .u64 t; cvta.to.shared.u64 t, %1; cvt.u32.u64 %0, t; }"
        : "=r"(a) : "l"(p));
    return a;
}
__device__ __forceinline__ uint32_t bf16x2_of(float v0, float v1) {
    uint32_t r;
    asm("cvt.rn.bf16x2.f32 %0, %1, %2;" : "=r"(r) : "f"(v1), "f"(v0));
    return r;
}
__device__ __forceinline__ uint32_t lds32(uint32_t addr) {
    uint32_t v;
    asm volatile("ld.shared.b32 %0, [%1];" : "=r"(v) : "r"(addr));
    return v;
}
__device__ __forceinline__ void stg128_cs(float* p, float4 v) {
    asm volatile("st.global.cs.v4.f32 [%0], {%1,%2,%3,%4};"
                 :: "l"(p), "f"(v.x), "f"(v.y), "f"(v.z), "f"(v.w) : "memory");
}
__device__ __forceinline__ void mma16816(float* c, const uint32_t* a, const uint32_t* b) {
    asm volatile(
        "mma.sync.aligned.m16n8k16.row.col.f32.bf16.bf16.f32 "
        "{%0,%1,%2,%3}, {%4,%5,%6,%7}, {%8,%9}, {%0,%1,%2,%3};"
        : "+f"(c[0]), "+f"(c[1]), "+f"(c[2]), "+f"(c[3])
        : "r"(a[0]), "r"(a[1]), "r"(a[2]), "r"(a[3]), "r"(b[0]), "r"(b[1]));
}
__device__ __forceinline__ float exp_acc(float x) {
    float m = __fmul_rn(x, 1.4426950408889634f);
    float t = __fmaf_rn(x, 1.925962991e-8f, m);
    float r;
    asm("ex2.approx.ftz.f32 %0, %1;" : "=f"(r) : "f"(t));
    return r;
}
__device__ __forceinline__ void split_store4(char* smem, uint32_t offHi, uint32_t offLo, float4 v) {
    uint32_t h01 = bf16x2_of(v.x, v.y);
    uint32_t h23 = bf16x2_of(v.z, v.w);
    float l0 = v.x - __uint_as_float(h01 << 16);
    float l1 = v.y - __uint_as_float(h01 & 0xFFFF0000u);
    float l2 = v.z - __uint_as_float(h23 << 16);
    float l3 = v.w - __uint_as_float(h23 & 0xFFFF0000u);
    *(uint2*)(smem + offHi) = make_uint2(h01, h23);
    *(uint2*)(smem + offLo) = make_uint2(bf16x2_of(l0, l1), bf16x2_of(l2, l3));
}
__device__ __forceinline__ void split2(float2 v, uint32_t& hi, uint32_t& lo) {
    hi = bf16x2_of(v.x, v.y);
    float l0 = v.x - __uint_as_float(hi << 16);
    float l1 = v.y - __uint_as_float(hi & 0xFFFF0000u);
    lo = bf16x2_of(l0, l1);
}

// ======================================================================
// Kernel 1: sg (fp64) -> [sync] -> prior+sigf (streaming .cs stores,
// drain during everything below) -> Q/K load+split -> QK^T MMA ->
// softmax -> series.
// ======================================================================
#define F_ST   72
#define F_QHI  0
#define F_QLO  9216
#define F_KHI  18432
#define F_KLO  92160
#define F_SG   165888            // 64 * 4
#define F_RED0 166144
#define F_RED1 167168
#define F_SMEM 168192

__global__ void __launch_bounds__(512, 1)
qk_softmax_prior_kernel(const float* __restrict__ q, const float* __restrict__ k,
                        const float* __restrict__ sigma,
                        float* __restrict__ series,
                        float* __restrict__ prior, float* __restrict__ sigf)
{
    extern __shared__ char smem[];
    const uint32_t sb = smem_u32(smem);
    const int tid  = threadIdx.x;
    const int wid  = tid >> 5;
    const int lane = tid & 31;
    const int wm   = wid >> 2;
    const int wn   = wid & 3;
    const int r    = lane >> 2;
    const int qc   = lane & 3;

    const int bh = blockIdx.y;
    const int b  = bh >> 3;
    const int h  = bh & 7;
    const int lt = blockIdx.x;
    const int lbase = lt * 64;

    // ---- sigma -> bandwidth (fp64, 64 threads) ----
    if (tid < 64) {
        int gl = lbase + tid;
        double xd = (double)sigma[((size_t)b * L_ + gl) * H_ + h];
        double sd = 1.0 / (1.0 + exp(-5.0 * xd));
        float sgm = (float)(sd + 1e-5);
        double P  = exp2((double)sgm * 1.5849625007211562);  // 3^sgm
        *(float*)(smem + F_SG + tid * 4) = (float)P - 1.0f;
    }
    __syncthreads();   // cheap: only sg pending

    // ---- prior + sigma_full FIRST (streaming stores drain during all
    //      later phases; .cs keeps them out of L2 so series stays hot) ----
    {
#pragma unroll
        for (int i = tid; i < 8192; i += 512) {
            int row = i >> 7, c4 = (i & 127) * 4;
            const float sg = *(const float*)(smem + F_SG + row * 4);
            const float cv   = __fdiv_rn(0.3989422804014327f, sg);
            const float rinv = __fdiv_rn(1.0f, __fmul_rn(2.0f, __fmul_rn(sg, sg)));
            const int gl = lbase + row;
            float d0 = (float)(gl - c4);
            float d1 = (float)(gl - c4 - 1);
            float d2 = (float)(gl - c4 - 2);
            float d3 = (float)(gl - c4 - 3);
            float4 pv;
            pv.x = __fmul_rn(cv, exp_acc(-__fmul_rn(__fmul_rn(d0, d0), rinv)));
            pv.y = __fmul_rn(cv, exp_acc(-__fmul_rn(__fmul_rn(d1, d1), rinv)));
            pv.z = __fmul_rn(cv, exp_acc(-__fmul_rn(__fmul_rn(d2, d2), rinv)));
            pv.w = __fmul_rn(cv, exp_acc(-__fmul_rn(__fmul_rn(d3, d3), rinv)));
            size_t base = ((size_t)bh * L_ + gl) * L_ + c4;
            stg128_cs(prior + base, pv);
            stg128_cs(sigf + base, make_float4(sg, sg, sg, sg));
        }
    }

    // ---- Q/K load + bf16 split into smem ----
    const float* qbase = q + (size_t)(b * L_ + lbase) * (H_ * E_) + h * E_;
    const float* kbase = k + (size_t)(b * L_) * (H_ * E_) + h * E_;
#pragma unroll
    for (int i = tid; i < 1024; i += 512) {
        int row = i >> 4, e4 = i & 15;
        uint32_t off = (uint32_t)row * (F_ST * 2) + e4 * 8;
        float4 va = *(const float4*)(qbase + (size_t)row * (H_ * E_) + e4 * 4);
        va.x *= 0.125f; va.y *= 0.125f; va.z *= 0.125f; va.w *= 0.125f;
        split_store4(smem, F_QHI + off, F_QLO + off, va);
    }
#pragma unroll
    for (int i = tid; i < 8192; i += 512) {
        int row = i >> 4, e4 = i & 15;
        uint32_t off = (uint32_t)row * (F_ST * 2) + e4 * 8;
        float4 vb = *(const float4*)(kbase + (size_t)row * (H_ * E_) + e4 * 4);
        split_store4(smem, F_KHI + off, F_KLO + off, vb);
    }
    __syncthreads();

    // ---- QK^T MMA (3-product bf16 split) ----
    float acc[16][4];
#pragma unroll
    for (int nb = 0; nb < 16; nb++)
#pragma unroll
        for (int x = 0; x < 4; x++) acc[nb][x] = 0.f;

    {
        const uint32_t abase[3] = {sb + F_QHI, sb + F_QHI, sb + F_QLO};
        const uint32_t bbase[3] = {sb + F_KHI, sb + F_KLO, sb + F_KHI};
#pragma unroll
        for (int pr = 0; pr < 3; pr++) {
            uint32_t Ab = abase[pr], Bb = bbase[pr];
#pragma unroll
            for (int ks = 0; ks < 4; ks++) {
                uint32_t kByte = ks * 32 + qc * 4;
                uint32_t a[4];
                uint32_t ad = Ab + (uint32_t)(wm * 16 + r) * (F_ST * 2) + kByte;
                a[0] = lds32(ad);
                a[1] = lds32(ad + 8 * F_ST * 2);
                a[2] = lds32(ad + 16);
                a[3] = lds32(ad + 8 * F_ST * 2 + 16);
#pragma unroll
                for (int nb = 0; nb < 16; nb++) {
                    uint32_t bd = Bb + (uint32_t)(wn * 128 + nb * 8 + r) * (F_ST * 2) + kByte;
                    uint32_t bf[2];
                    bf[0] = lds32(bd);
                    bf[1] = lds32(bd + 16);
                    mma16816(acc[nb], a, bf);
                }
            }
        }
    }

    // ---- softmax over 512 cols ----
    const int row0 = wm * 16 + r;
    const int row1 = row0 + 8;

    float mx0 = -1e30f, mx1 = -1e30f;
#pragma unroll
    for (int nb = 0; nb < 16; nb++) {
        mx0 = fmaxf(mx0, fmaxf(acc[nb][0], acc[nb][1]));
        mx1 = fmaxf(mx1, fmaxf(acc[nb][2], acc[nb][3]));
    }
#pragma unroll
    for (int o = 1; o <= 2; o <<= 1) {
        mx0 = fmaxf(mx0, __shfl_xor_sync(0xffffffffu, mx0, o));
        mx1 = fmaxf(mx1, __shfl_xor_sync(0xffffffffu, mx1, o));
    }
    if (qc == 0) {
        *(float*)(smem + F_RED0 + (row0 * 4 + wn) * 4) = mx0;
        *(float*)(smem + F_RED0 + (row1 * 4 + wn) * 4) = mx1;
    }
    __syncthreads();
    {
        const float* rd = (const float*)(smem + F_RED0);
        mx0 = fmaxf(fmaxf(rd[row0 * 4 + 0], rd[row0 * 4 + 1]),
                    fmaxf(rd[row0 * 4 + 2], rd[row0 * 4 + 3]));
        mx1 = fmaxf(fmaxf(rd[row1 * 4 + 0], rd[row1 * 4 + 1]),
                    fmaxf(rd[row1 * 4 + 2], rd[row1 * 4 + 3]));
    }

    float s0 = 0.f, s1 = 0.f;
#pragma unroll
    for (int nb = 0; nb < 16; nb++) {
        acc[nb][0] = exp_acc(acc[nb][0] - mx0); s0 += acc[nb][0];
        acc[nb][1] = exp_acc(acc[nb][1] - mx0); s0 += acc[nb][1];
        acc[nb][2] = exp_acc(acc[nb][2] - mx1); s1 += acc[nb][2];
        acc[nb][3] = exp_acc(acc[nb][3] - mx1); s1 += acc[nb][3];
    }
#pragma unroll
    for (int o = 1; o <= 2; o <<= 1) {
        s0 += __shfl_xor_sync(0xffffffffu, s0, o);
        s1 += __shfl_xor_sync(0xffffffffu, s1, o);
    }
    if (qc == 0) {
        *(float*)(smem + F_RED1 + (row0 * 4 + wn) * 4) = s0;
        *(float*)(smem + F_RED1 + (row1 * 4 + wn) * 4) = s1;
    }
    __syncthreads();
    {
        const float* rd = (const float*)(smem + F_RED1);
        s0 = (rd[row0 * 4 + 0] + rd[row0 * 4 + 1]) + (rd[row0 * 4 + 2] + rd[row0 * 4 + 3]);
        s1 = (rd[row1 * 4 + 0] + rd[row1 * 4 + 1]) + (rd[row1 * 4 + 2] + rd[row1 * 4 + 3]);
    }
    const float inv0 = __fdiv_rn(1.f, s0);
    const float inv1 = __fdiv_rn(1.f, s1);

    float* o0 = series + ((size_t)bh * L_ + lbase + row0) * L_ + wn * 128 + qc * 2;
    float* o1 = series + ((size_t)bh * L_ + lbase + row1) * L_ + wn * 128 + qc * 2;
#pragma unroll
    for (int nb = 0; nb < 16; nb++) {
        *(float2*)(o0 + nb * 8) = make_float2(acc[nb][0] * inv0, acc[nb][1] * inv0);
        *(float2*)(o1 + nb * 8) = make_float2(acc[nb][2] * inv1, acc[nb][3] * inv1);
    }
}

// ======================================================================
// Kernel 3 (pv3 + prefetch): V[b,l,h,d] = sum_s P[bh,l,s] * values[..]
// One CTA per bh: 512 rows x 64 d, 512 thr, warp = 32 rows.
// Double-buffered global P loads to hide L2/DRAM latency.
// ======================================================================
#define PVB_ST  1040
#define PVB_HI  0
#define PVB_LO  66560
#define PVB_SMEM 133120

__global__ void __launch_bounds__(512, 1)
pv3_kernel(const float* __restrict__ p, const float* __restrict__ v,
           float* __restrict__ out)
{
    extern __shared__ char smem[];
    const uint32_t sb = smem_u32(smem);
    const int tid  = threadIdx.x;
    const int wid  = tid >> 5;
    const int lane = tid & 31;
    const int r    = lane >> 2;
    const int qc   = lane & 3;

    const int bh = blockIdx.x;
    const int b  = bh >> 3;
    const int h  = bh & 7;

    const float* vbase = v + (size_t)b * L_ * H_ * E_ + h * E_;

#pragma unroll
    for (int i = tid; i < 8192; i += 512) {
        int s = i >> 4, d4 = i & 15;
        float4 vv = *(const float4*)(vbase + (size_t)s * (H_ * E_) + d4 * 4);
        float xs[4] = {vv.x, vv.y, vv.z, vv.w};
#pragma unroll
        for (int j = 0; j < 4; j++) {
            __nv_bfloat16 hb = __float2bfloat16(xs[j]);
            float hf = __bfloat162float(hb);
            __nv_bfloat16 lb = __float2bfloat16(xs[j] - hf);
            uint32_t off = (uint32_t)(d4 * 4 + j) * PVB_ST + s * 2;
            *(__nv_bfloat16*)(smem + PVB_HI + off) = hb;
            *(__nv_bfloat16*)(smem + PVB_LO + off) = lb;
        }
    }
    __syncthreads();

    const float* prow = p + ((size_t)bh * L_ + wid * 32) * L_;

    float acc[2][8][4];
#pragma unroll
    for (int m = 0; m < 2; m++)
#pragma unroll
        for (int nb = 0; nb < 8; nb++)
#pragma unroll
            for (int x = 0; x < 4; x++) acc[m][nb][x] = 0.f;

    // prefetch ks = 0
    float2 cur[2][4];
    {
        const int c0 = qc * 2;
#pragma unroll
        for (int m = 0; m < 2; m++) {
            cur[m][0] = *(const float2*)(prow + (size_t)(m * 16 + r) * L_ + c0);
            cur[m][1] = *(const float2*)(prow + (size_t)(m * 16 + r + 8) * L_ + c0);
            cur[m][2] = *(const float2*)(prow + (size_t)(m * 16 + r) * L_ + c0 + 8);
            cur[m][3] = *(const float2*)(prow + (size_t)(m * 16 + r + 8) * L_ + c0 + 8);
        }
    }

#pragma unroll 2
    for (int ks = 0; ks < 32; ks++) {
        // prefetch ks+1
        float2 nxt[2][4];
        if (ks < 31) {
            const int c1 = (ks + 1) * 16 + qc * 2;
#pragma unroll
            for (int m = 0; m < 2; m++) {
                nxt[m][0] = *(const float2*)(prow + (size_t)(m * 16 + r) * L_ + c1);
                nxt[m][1] = *(const float2*)(prow + (size_t)(m * 16 + r + 8) * L_ + c1);
                nxt[m][2] = *(const float2*)(prow + (size_t)(m * 16 + r) * L_ + c1 + 8);
                nxt[m][3] = *(const float2*)(prow + (size_t)(m * 16 + r + 8) * L_ + c1 + 8);
            }
        }

        uint32_t ahi[2][4], alo[2][4];
#pragma unroll
        for (int m = 0; m < 2; m++) {
            split2(cur[m][0], ahi[m][0], alo[m][0]);
            split2(cur[m][1], ahi[m][1], alo[m][1]);
            split2(cur[m][2], ahi[m][2], alo[m][2]);
            split2(cur[m][3], ahi[m][3], alo[m][3]);
        }

        const uint32_t kByte = (uint32_t)ks * 32 + qc * 4;
#pragma unroll
        for (int nb = 0; nb < 8; nb++) {
            uint32_t bd = sb + (uint32_t)(nb * 8 + r) * PVB_ST + kByte;
            uint32_t bhi[2], blo[2];
            bhi[0] = lds32(bd + PVB_HI);
            bhi[1] = lds32(bd + PVB_HI + 16);
            blo[0] = lds32(bd + PVB_LO);
            blo[1] = lds32(bd + PVB_LO + 16);
#pragma unroll
            for (int m = 0; m < 2; m++) {
                mma16816(acc[m][nb], ahi[m], bhi);
                mma16816(acc[m][nb], alo[m], bhi);
                mma16816(acc[m][nb], ahi[m], blo);
            }
        }

        if (ks < 31) {
#pragma unroll
            for (int m = 0; m < 2; m++)
#pragma unroll
                for (int j = 0; j < 4; j++) cur[m][j] = nxt[m][j];
        }
    }

#pragma unroll
    for (int m = 0; m < 2; m++) {
        const int l0 = wid * 32 + m * 16 + r;
        float* ob0 = out + (((size_t)b * L_ + l0) * H_ + h) * E_ + qc * 2;
        float* ob1 = out + (((size_t)b * L_ + l0 + 8) * H_ + h) * E_ + qc * 2;
#pragma unroll
        for (int nb = 0; nb < 8; nb++) {
            *(float2*)(ob0 + nb * 8) = make_float2(acc[m][nb][0], acc[m][nb][1]);
            *(float2*)(ob1 + nb * 8) = make_float2(acc[m][nb][2], acc[m][nb][3]);
        }
    }
}

// ======================================================================
extern "C" void kernel_launch(void* const* d_in, const int* in_sizes, int n_in,
                              void* d_out, int out_size)
{
    const float* q     = (const float*)d_in[0];
    const float* k     = (const float*)d_in[1];
    const float* v     = (const float*)d_in[2];
    const float* sigma = (const float*)d_in[3];

    float* out    = (float*)d_out;
    float* Vout   = out;                                        // [B,L,H,E]
    float* series = Vout + (size_t)B_ * L_ * H_ * E_;           // [B,H,L,L]
    float* prior  = series + (size_t)BH_ * L_ * L_;             // [B,H,L,L]
    float* sigf   = prior + (size_t)BH_ * L_ * L_;              // [B,H,L,L]

    cudaFuncSetAttribute(qk_softmax_prior_kernel, cudaFuncAttributeMaxDynamicSharedMemorySize, F_SMEM);
    cudaFuncSetAttribute(pv3_kernel, cudaFuncAttributeMaxDynamicSharedMemorySize, PVB_SMEM);

    dim3 g1(8, BH_);
    qk_softmax_prior_kernel<<<g1, 512, F_SMEM>>>(q, k, sigma, series, prior, sigf);

    pv3_kernel<<<BH_, 512, PVB_SMEM>>>(series, v, Vout);
}

// round 12
// speedup vs baseline: 1.1968x; 1.0339x over previous
#include <cuda_runtime.h>
#include <cuda_bf16.h>
#include <cstdint>

// Problem dims
#define B_ 16
#define L_ 512
#define H_ 8
#define E_ 64
#define BH_ (B_ * H_)          // 128

// ===================== helpers =====================
__device__ __forceinline__ uint32_t smem_u32(const void* p) {
    uint32_t a;
    asm("{ .reg .u64 t; cvta.to.shared.u64 t, %1; cvt.u32.u64 %0, t; }"
        : "=r"(a) : "l"(p));
    return a;
}
__device__ __forceinline__ uint32_t bf16x2_of(float v0, float v1) {
    uint32_t r;
    asm("cvt.rn.bf16x2.f32 %0, %1, %2;" : "=r"(r) : "f"(v1), "f"(v0));
    return r;
}
__device__ __forceinline__ uint32_t lds32(uint32_t addr) {
    uint32_t v;
    asm volatile("ld.shared.b32 %0, [%1];" : "=r"(v) : "r"(addr));
    return v;
}
__device__ __forceinline__ void mma16816(float* c, const uint32_t* a, const uint32_t* b) {
    asm volatile(
        "mma.sync.aligned.m16n8k16.row.col.f32.bf16.bf16.f32 "
        "{%0,%1,%2,%3}, {%4,%5,%6,%7}, {%8,%9}, {%0,%1,%2,%3};"
        : "+f"(c[0]), "+f"(c[1]), "+f"(c[2]), "+f"(c[3])
        : "r"(a[0]), "r"(a[1]), "r"(a[2]), "r"(a[3]), "r"(b[0]), "r"(b[1]));
}
__device__ __forceinline__ float exp_acc(float x) {
    float m = __fmul_rn(x, 1.4426950408889634f);
    float t = __fmaf_rn(x, 1.925962991e-8f, m);
    float r;
    asm("ex2.approx.ftz.f32 %0, %1;" : "=f"(r) : "f"(t));
    return r;
}
__device__ __forceinline__ void split_store4(char* smem, uint32_t offHi, uint32_t offLo, float4 v) {
    uint32_t h01 = bf16x2_of(v.x, v.y);
    uint32_t h23 = bf16x2_of(v.z, v.w);
    float l0 = v.x - __uint_as_float(h01 << 16);
    float l1 = v.y - __uint_as_float(h01 & 0xFFFF0000u);
    float l2 = v.z - __uint_as_float(h23 << 16);
    float l3 = v.w - __uint_as_float(h23 & 0xFFFF0000u);
    *(uint2*)(smem + offHi) = make_uint2(h01, h23);
    *(uint2*)(smem + offLo) = make_uint2(bf16x2_of(l0, l1), bf16x2_of(l2, l3));
}
__device__ __forceinline__ void split2(float2 v, uint32_t& hi, uint32_t& lo) {
    hi = bf16x2_of(v.x, v.y);
    float l0 = v.x - __uint_as_float(hi << 16);
    float l1 = v.y - __uint_as_float(hi & 0xFFFF0000u);
    lo = bf16x2_of(l0, l1);
}

// ======================================================================
// Kernel 1: CTA = 32 l-rows x 512 s-cols, 256 thr, 2 CTAs/SM.
// K processed in two 256-row chunks (smem 84 KB/CTA).
// Order (per R9): sg -> Q + K-chunk loads -> prior -> MMA -> softmax.
// ======================================================================
#define F_QHI  0                   // 32*144 = 4608
#define F_QLO  4608
#define F_KHI  9216                // 256*144 = 36864
#define F_KLO  46080
#define F_SG   82944               // 32*4
#define F_RED0 83072               // 32 rows * 4 wn * 4B
#define F_RED1 83584
#define F_SMEM 84096

#define F_ST   72

__global__ void __launch_bounds__(256, 2)
qk_softmax_prior_kernel(const float* __restrict__ q, const float* __restrict__ k,
                        const float* __restrict__ sigma,
                        float* __restrict__ series,
                        float* __restrict__ prior, float* __restrict__ sigf)
{
    extern __shared__ char smem[];
    const uint32_t sb = smem_u32(smem);
    const int tid  = threadIdx.x;
    const int wid  = tid >> 5;
    const int lane = tid & 31;
    const int wm   = wid >> 2;       // 2 m-warps (16 rows each)
    const int wn   = wid & 3;        // 4 n-warps (64 cols per chunk each)
    const int r    = lane >> 2;
    const int qc   = lane & 3;

    const int bh = blockIdx.y;
    const int b  = bh >> 3;
    const int h  = bh & 7;
    const int lt = blockIdx.x;       // 16 tiles of 32 rows
    const int lbase = lt * 32;

    // ---- sigma -> bandwidth (fp64, 32 threads) ----
    if (tid < 32) {
        int gl = lbase + tid;
        double xd = (double)sigma[((size_t)b * L_ + gl) * H_ + h];
        double sd = 1.0 / (1.0 + exp(-5.0 * xd));
        float sgm = (float)(sd + 1e-5);
        double P  = exp2((double)sgm * 1.5849625007211562);  // 3^sgm
        *(float*)(smem + F_SG + tid * 4) = (float)P - 1.0f;
    }

    // ---- Q tile 32x64 (scaled), split hi/lo ----
    const float* qbase = q + (size_t)(b * L_ + lbase) * (H_ * E_) + h * E_;
    const float* kbase = k + (size_t)(b * L_) * (H_ * E_) + h * E_;
#pragma unroll
    for (int i = tid; i < 512; i += 256) {
        int row = i >> 4, e4 = i & 15;
        uint32_t off = (uint32_t)row * (F_ST * 2) + e4 * 8;
        float4 va = *(const float4*)(qbase + (size_t)row * (H_ * E_) + e4 * 4);
        va.x *= 0.125f; va.y *= 0.125f; va.z *= 0.125f; va.w *= 0.125f;
        split_store4(smem, F_QHI + off, F_QLO + off, va);
    }

    float acc[16][4];
#pragma unroll
    for (int nb = 0; nb < 16; nb++)
#pragma unroll
        for (int x = 0; x < 4; x++) acc[nb][x] = 0.f;

    // ---- two K chunks of 256 s-rows ----
#pragma unroll
    for (int ch = 0; ch < 2; ch++) {
        // load K chunk, split hi/lo
#pragma unroll
        for (int i = tid; i < 4096; i += 256) {
            int row = i >> 4, e4 = i & 15;
            uint32_t off = (uint32_t)row * (F_ST * 2) + e4 * 8;
            float4 vb = *(const float4*)(kbase + (size_t)(ch * 256 + row) * (H_ * E_) + e4 * 4);
            split_store4(smem, F_KHI + off, F_KLO + off, vb);
        }
        __syncthreads();

        // prior + sigma_full after first sync (R9 ordering: stores drain
        // during MMA). Only on chunk 0.
        if (ch == 0) {
#pragma unroll
            for (int i = tid; i < 4096; i += 256) {
                int row = i >> 7, c4 = (i & 127) * 4;
                const float sg = *(const float*)(smem + F_SG + row * 4);
                const float cv   = __fdiv_rn(0.3989422804014327f, sg);
                const float rinv = __fdiv_rn(1.0f, __fmul_rn(2.0f, __fmul_rn(sg, sg)));
                const int gl = lbase + row;
                float d0 = (float)(gl - c4);
                float d1 = (float)(gl - c4 - 1);
                float d2 = (float)(gl - c4 - 2);
                float d3 = (float)(gl - c4 - 3);
                float4 pv;
                pv.x = __fmul_rn(cv, exp_acc(-__fmul_rn(__fmul_rn(d0, d0), rinv)));
                pv.y = __fmul_rn(cv, exp_acc(-__fmul_rn(__fmul_rn(d1, d1), rinv)));
                pv.z = __fmul_rn(cv, exp_acc(-__fmul_rn(__fmul_rn(d2, d2), rinv)));
                pv.w = __fmul_rn(cv, exp_acc(-__fmul_rn(__fmul_rn(d3, d3), rinv)));
                size_t base = ((size_t)bh * L_ + gl) * L_ + c4;
                *(float4*)(prior + base) = pv;
                *(float4*)(sigf + base)  = make_float4(sg, sg, sg, sg);
            }
        }

        // MMA over this chunk (3-product bf16 split)
        const uint32_t abase[3] = {sb + F_QHI, sb + F_QHI, sb + F_QLO};
        const uint32_t bbase[3] = {sb + F_KHI, sb + F_KLO, sb + F_KHI};
#pragma unroll
        for (int pr = 0; pr < 3; pr++) {
            uint32_t Ab = abase[pr], Bb = bbase[pr];
#pragma unroll
            for (int ks = 0; ks < 4; ks++) {
                uint32_t kByte = ks * 32 + qc * 4;
                uint32_t a[4];
                uint32_t ad = Ab + (uint32_t)(wm * 16 + r) * (F_ST * 2) + kByte;
                a[0] = lds32(ad);
                a[1] = lds32(ad + 8 * F_ST * 2);
                a[2] = lds32(ad + 16);
                a[3] = lds32(ad + 8 * F_ST * 2 + 16);
#pragma unroll
                for (int nb = 0; nb < 8; nb++) {
                    uint32_t bd = Bb + (uint32_t)(wn * 64 + nb * 8 + r) * (F_ST * 2) + kByte;
                    uint32_t bf[2];
                    bf[0] = lds32(bd);
                    bf[1] = lds32(bd + 16);
                    mma16816(acc[ch * 8 + nb], a, bf);
                }
            }
        }
        __syncthreads();   // before overwriting K chunk
    }

    // ---- softmax over 512 cols ----
    const int row0 = wm * 16 + r;
    const int row1 = row0 + 8;

    float mx0 = -1e30f, mx1 = -1e30f;
#pragma unroll
    for (int nb = 0; nb < 16; nb++) {
        mx0 = fmaxf(mx0, fmaxf(acc[nb][0], acc[nb][1]));
        mx1 = fmaxf(mx1, fmaxf(acc[nb][2], acc[nb][3]));
    }
#pragma unroll
    for (int o = 1; o <= 2; o <<= 1) {
        mx0 = fmaxf(mx0, __shfl_xor_sync(0xffffffffu, mx0, o));
        mx1 = fmaxf(mx1, __shfl_xor_sync(0xffffffffu, mx1, o));
    }
    if (qc == 0) {
        *(float*)(smem + F_RED0 + (row0 * 4 + wn) * 4) = mx0;
        *(float*)(smem + F_RED0 + (row1 * 4 + wn) * 4) = mx1;
    }
    __syncthreads();
    {
        const float* rd = (const float*)(smem + F_RED0);
        mx0 = fmaxf(fmaxf(rd[row0 * 4 + 0], rd[row0 * 4 + 1]),
                    fmaxf(rd[row0 * 4 + 2], rd[row0 * 4 + 3]));
        mx1 = fmaxf(fmaxf(rd[row1 * 4 + 0], rd[row1 * 4 + 1]),
                    fmaxf(rd[row1 * 4 + 2], rd[row1 * 4 + 3]));
    }

    float s0 = 0.f, s1 = 0.f;
#pragma unroll
    for (int nb = 0; nb < 16; nb++) {
        acc[nb][0] = exp_acc(acc[nb][0] - mx0); s0 += acc[nb][0];
        acc[nb][1] = exp_acc(acc[nb][1] - mx0); s0 += acc[nb][1];
        acc[nb][2] = exp_acc(acc[nb][2] - mx1); s1 += acc[nb][2];
        acc[nb][3] = exp_acc(acc[nb][3] - mx1); s1 += acc[nb][3];
    }
#pragma unroll
    for (int o = 1; o <= 2; o <<= 1) {
        s0 += __shfl_xor_sync(0xffffffffu, s0, o);
        s1 += __shfl_xor_sync(0xffffffffu, s1, o);
    }
    if (qc == 0) {
        *(float*)(smem + F_RED1 + (row0 * 4 + wn) * 4) = s0;
        *(float*)(smem + F_RED1 + (row1 * 4 + wn) * 4) = s1;
    }
    __syncthreads();
    {
        const float* rd = (const float*)(smem + F_RED1);
        s0 = (rd[row0 * 4 + 0] + rd[row0 * 4 + 1]) + (rd[row0 * 4 + 2] + rd[row0 * 4 + 3]);
        s1 = (rd[row1 * 4 + 0] + rd[row1 * 4 + 1]) + (rd[row1 * 4 + 2] + rd[row1 * 4 + 3]);
    }
    const float inv0 = __fdiv_rn(1.f, s0);
    const float inv1 = __fdiv_rn(1.f, s1);

    // series writes: col = ch*256 + wn*64 + nb8*8 + qc*2
    float* r0p = series + ((size_t)bh * L_ + lbase + row0) * L_;
    float* r1p = series + ((size_t)bh * L_ + lbase + row1) * L_;
#pragma unroll
    for (int nb = 0; nb < 16; nb++) {
        int col = (nb >> 3) * 256 + wn * 64 + (nb & 7) * 8 + qc * 2;
        *(float2*)(r0p + col) = make_float2(acc[nb][0] * inv0, acc[nb][1] * inv0);
        *(float2*)(r1p + col) = make_float2(acc[nb][2] * inv1, acc[nb][3] * inv1);
    }
}

// ======================================================================
// Kernel 3 (pv3, exact R9 version): V = P @ values
// One CTA per bh: 512 rows x 64 d, 512 thr, warp = 32 rows.
// ======================================================================
#define PVB_ST  1040
#define PVB_HI  0
#define PVB_LO  66560
#define PVB_SMEM 133120

__global__ void __launch_bounds__(512, 1)
pv3_kernel(const float* __restrict__ p, const float* __restrict__ v,
           float* __restrict__ out)
{
    extern __shared__ char smem[];
    const uint32_t sb = smem_u32(smem);
    const int tid  = threadIdx.x;
    const int wid  = tid >> 5;
    const int lane = tid & 31;
    const int r    = lane >> 2;
    const int qc   = lane & 3;

    const int bh = blockIdx.x;
    const int b  = bh >> 3;
    const int h  = bh & 7;

    const float* vbase = v + (size_t)b * L_ * H_ * E_ + h * E_;

#pragma unroll
    for (int i = tid; i < 8192; i += 512) {
        int s = i >> 4, d4 = i & 15;
        float4 vv = *(const float4*)(vbase + (size_t)s * (H_ * E_) + d4 * 4);
        float xs[4] = {vv.x, vv.y, vv.z, vv.w};
#pragma unroll
        for (int j = 0; j < 4; j++) {
            __nv_bfloat16 hb = __float2bfloat16(xs[j]);
            float hf = __bfloat162float(hb);
            __nv_bfloat16 lb = __float2bfloat16(xs[j] - hf);
            uint32_t off = (uint32_t)(d4 * 4 + j) * PVB_ST + s * 2;
            *(__nv_bfloat16*)(smem + PVB_HI + off) = hb;
            *(__nv_bfloat16*)(smem + PVB_LO + off) = lb;
        }
    }
    __syncthreads();

    const float* prow = p + ((size_t)bh * L_ + wid * 32) * L_;

    float acc[2][8][4];
#pragma unroll
    for (int m = 0; m < 2; m++)
#pragma unroll
        for (int nb = 0; nb < 8; nb++)
#pragma unroll
            for (int x = 0; x < 4; x++) acc[m][nb][x] = 0.f;

#pragma unroll 2
    for (int ks = 0; ks < 32; ks++) {
        const int c0 = ks * 16 + qc * 2;
        uint32_t ahi[2][4], alo[2][4];
#pragma unroll
        for (int m = 0; m < 2; m++) {
            float2 x0 = *(const float2*)(prow + (size_t)(m * 16 + r) * L_ + c0);
            float2 x1 = *(const float2*)(prow + (size_t)(m * 16 + r + 8) * L_ + c0);
            float2 x2 = *(const float2*)(prow + (size_t)(m * 16 + r) * L_ + c0 + 8);
            float2 x3 = *(const float2*)(prow + (size_t)(m * 16 + r + 8) * L_ + c0 + 8);
            split2(x0, ahi[m][0], alo[m][0]);
            split2(x1, ahi[m][1], alo[m][1]);
            split2(x2, ahi[m][2], alo[m][2]);
            split2(x3, ahi[m][3], alo[m][3]);
        }

        const uint32_t kByte = (uint32_t)ks * 32 + qc * 4;
#pragma unroll
        for (int nb = 0; nb < 8; nb++) {
            uint32_t bd = sb + (uint32_t)(nb * 8 + r) * PVB_ST + kByte;
            uint32_t bhi[2], blo[2];
            bhi[0] = lds32(bd + PVB_HI);
            bhi[1] = lds32(bd + PVB_HI + 16);
            blo[0] = lds32(bd + PVB_LO);
            blo[1] = lds32(bd + PVB_LO + 16);
#pragma unroll
            for (int m = 0; m < 2; m++) {
                mma16816(acc[m][nb], ahi[m], bhi);
                mma16816(acc[m][nb], alo[m], bhi);
                mma16816(acc[m][nb], ahi[m], blo);
            }
        }
    }

#pragma unroll
    for (int m = 0; m < 2; m++) {
        const int l0 = wid * 32 + m * 16 + r;
        float* ob0 = out + (((size_t)b * L_ + l0) * H_ + h) * E_ + qc * 2;
        float* ob1 = out + (((size_t)b * L_ + l0 + 8) * H_ + h) * E_ + qc * 2;
#pragma unroll
        for (int nb = 0; nb < 8; nb++) {
            *(float2*)(ob0 + nb * 8) = make_float2(acc[m][nb][0], acc[m][nb][1]);
            *(float2*)(ob1 + nb * 8) = make_float2(acc[m][nb][2], acc[m][nb][3]);
        }
    }
}

// ======================================================================
extern "C" void kernel_launch(void* const* d_in, const int* in_sizes, int n_in,
                              void* d_out, int out_size)
{
    const float* q     = (const float*)d_in[0];
    const float* k     = (const float*)d_in[1];
    const float* v     = (const float*)d_in[2];
    const float* sigma = (const float*)d_in[3];

    float* out    = (float*)d_out;
    float* Vout   = out;                                        // [B,L,H,E]
    float* series = Vout + (size_t)B_ * L_ * H_ * E_;           // [B,H,L,L]
    float* prior  = series + (size_t)BH_ * L_ * L_;             // [B,H,L,L]
    float* sigf   = prior + (size_t)BH_ * L_ * L_;              // [B,H,L,L]

    cudaFuncSetAttribute(qk_softmax_prior_kernel, cudaFuncAttributeMaxDynamicSharedMemorySize, F_SMEM);
    cudaFuncSetAttribute(pv3_kernel, cudaFuncAttributeMaxDynamicSharedMemorySize, PVB_SMEM);

    dim3 g1(16, BH_);
    qk_softmax_prior_kernel<<<g1, 256, F_SMEM>>>(q, k, sigma, series, prior, sigf);

    pv3_kernel<<<BH_, 512, PVB_SMEM>>>(series, v, Vout);
}